// round 16
// baseline (speedup 1.0000x reference)
#include <cuda_runtime.h>

// Problem constants
#define B_SZ   2
#define S_LEN  2048
#define D_MOD  1024
#define HEADS  16
#define DHEAD  64
#define MROWS  (B_SZ * S_LEN)                                 // 4096
#define OUT_ELEMS  ((long)MROWS * D_MOD)                      // 4194304
#define ATTN_ELEMS ((long)B_SZ * HEADS * S_LEN * S_LEN)       // 134217728

// Scratch (static __device__ arrays: allocation-free per harness rules)
__device__ float g_q[MROWS * D_MOD];
__device__ float g_k[MROWS * D_MOD];
__device__ float g_v[MROWS * D_MOD];
__device__ float g_ctx[MROWS * D_MOD];
__device__ float g_attn_scratch[ATTN_ELEMS];

// ---------------------------------------------------------------------------
// helpers
// ---------------------------------------------------------------------------
__device__ __forceinline__ unsigned f2tf(float f) {
    unsigned u;
    asm("cvt.rna.tf32.f32 %0, %1;" : "=r"(u) : "f"(f));
    return u;
}
__device__ __forceinline__ uint4 cvt4(float4 f) {
    return make_uint4(f2tf(f.x), f2tf(f.y), f2tf(f.z), f2tf(f.w));
}
__device__ __forceinline__ void mma8(float* d, const unsigned* a, unsigned b0, unsigned b1) {
    asm volatile(
        "mma.sync.aligned.m16n8k8.row.col.f32.tf32.tf32.f32 "
        "{%0,%1,%2,%3}, {%4,%5,%6,%7}, {%8,%9}, {%0,%1,%2,%3};\n"
        : "+f"(d[0]), "+f"(d[1]), "+f"(d[2]), "+f"(d[3])
        : "r"(a[0]), "r"(a[1]), "r"(a[2]), "r"(a[3]), "r"(b0), "r"(b1));
}

// ---------------------------------------------------------------------------
// proj_mma: C[m][n] = A[m][k] * W[n][k] + bias[n]   (GEMM-NT)  — proven R1/R2
// ---------------------------------------------------------------------------
__global__ __launch_bounds__(256, 2) void proj_mma(
    const float* __restrict__ A, const float* __restrict__ W,
    const float* __restrict__ bias, float* __restrict__ C)
{
    __shared__ unsigned As[128][36];
    __shared__ unsigned Ws[128][36];

    const int tid = threadIdx.x;
    const int wid = tid >> 5, lane = tid & 31;
    const int g = lane >> 2, c = lane & 3;
    const int wm = wid >> 2;
    const int wn = wid & 3;
    const int m0 = blockIdx.y * 128, n0 = blockIdx.x * 128;

    float acc[4][4][4] = {};

    for (int k0 = 0; k0 < D_MOD; k0 += 32) {
        #pragma unroll
        for (int i = 0; i < 4; i++) {
            int idx = tid + i * 256;
            int row = idx >> 3, c4 = (idx & 7) * 4;
            float4 fa = *(const float4*)&A[(long)(m0 + row) * D_MOD + k0 + c4];
            float4 fw = *(const float4*)&W[(long)(n0 + row) * D_MOD + k0 + c4];
            *(uint4*)&As[row][c4] = cvt4(fa);
            *(uint4*)&Ws[row][c4] = cvt4(fw);
        }
        __syncthreads();

        #pragma unroll
        for (int ks = 0; ks < 4; ks++) {
            int kk = ks * 8;
            unsigned af[4][4], bf[4][2];
            #pragma unroll
            for (int mt = 0; mt < 4; mt++) {
                int r = wm * 64 + mt * 16 + g;
                af[mt][0] = As[r][kk + c];     af[mt][1] = As[r + 8][kk + c];
                af[mt][2] = As[r][kk + c + 4]; af[mt][3] = As[r + 8][kk + c + 4];
            }
            #pragma unroll
            for (int nt = 0; nt < 4; nt++) {
                int n = wn * 32 + nt * 8 + g;
                bf[nt][0] = Ws[n][kk + c];
                bf[nt][1] = Ws[n][kk + c + 4];
            }
            #pragma unroll
            for (int mt = 0; mt < 4; mt++)
                #pragma unroll
                for (int nt = 0; nt < 4; nt++)
                    mma8(acc[mt][nt], af[mt], bf[nt][0], bf[nt][1]);
        }
        __syncthreads();
    }

    #pragma unroll
    for (int nt = 0; nt < 4; nt++) {
        int col = n0 + wn * 32 + nt * 8 + 2 * c;
        float b0 = bias[col], b1 = bias[col + 1];
        #pragma unroll
        for (int mt = 0; mt < 4; mt++) {
            int r0 = m0 + wm * 64 + mt * 16 + g;
            float2 v0 = {acc[mt][nt][0] + b0, acc[mt][nt][1] + b1};
            float2 v1 = {acc[mt][nt][2] + b0, acc[mt][nt][3] + b1};
            *(float2*)&C[(long)r0 * D_MOD + col]       = v0;
            *(float2*)&C[(long)(r0 + 8) * D_MOD + col] = v1;
        }
    }
}

// ---------------------------------------------------------------------------
// Fused attention v4b: identical to R10 except VP row stride 68 -> 132
// (V tile is 64 n-rows x 128 packed k-words; 68 caused row overlap = R11 bug).
//  (a) fragment-packed smem: k-pairs (k, k+4) adjacent -> LDS.64 fragments
//      pos(k) = 8*(k/8) + 2*(k%4) + ((k%8)/4)
//  (b) register prefetch of next K tile (LDG overlaps MMA); V loaded mid-iter
// ---------------------------------------------------------------------------
#define QS_OFF   0                        // 128*68*4  = 34816
#define KS_OFF   34816                    // 128*68*4  = 34816
#define VS_OFF   69632                    // 64*132*4  = 33792
#define PS_OFF   103424                   // 128*36*4  = 18432
#define MSK_OFF  121856                   // 8192
#define SMEM_BYTES 130048

__global__ __launch_bounds__(256) void fused_attn(
    const float* __restrict__ q, const float* __restrict__ k,
    const float* __restrict__ v, const int* __restrict__ mask,
    float* __restrict__ attn, float* __restrict__ ctx)
{
    extern __shared__ char sm[];
    unsigned (*QP)[68]  = (unsigned(*)[68])(sm + QS_OFF);    // [128 m][64 k packed]
    unsigned (*KP)[68]  = (unsigned(*)[68])(sm + KS_OFF);    // [128 n][64 k packed]
    unsigned (*VP)[132] = (unsigned(*)[132])(sm + VS_OFF);   // [64 n][128 k packed]
    unsigned (*Ps)[36]  = (unsigned(*)[36])(sm + PS_OFF);    // [128 m][32 k] plain
    int* Msk = (int*)(sm + MSK_OFF);

    const int bh = blockIdx.y;
    const int b = bh >> 4, h = bh & 15;
    const float* qh = q + (long)b * S_LEN * D_MOD + h * DHEAD;
    const float* kh = k + (long)b * S_LEN * D_MOD + h * DHEAD;
    const float* vh = v + (long)b * S_LEN * D_MOD + h * DHEAD;
    float* attn_bh = attn + (long)bh * S_LEN * S_LEN;

    const int tid = threadIdx.x;
    const int wid = tid >> 5, lane = tid & 31;
    const int g = lane >> 2, c = lane & 3;
    const int m0 = blockIdx.x * 128;
    const int r = wid * 16 + g;        // warp-local rows r and r+8

    for (int j = tid; j < S_LEN; j += 256)
        Msk[j] = mask[b * S_LEN + j];

    // ---- Q tile: load + pack (one-time) ----
    #pragma unroll
    for (int u = 0; u < 4; u++) {
        int bi = tid + u * 256;
        int row = bi >> 3, blk = bi & 7;
        const float* p = &qh[(long)(m0 + row) * D_MOD + blk * 8];
        float4 b0 = *(const float4*)p;
        float4 b1 = *(const float4*)(p + 4);
        *(uint4*)&QP[row][blk * 8]     = make_uint4(f2tf(b0.x), f2tf(b1.x), f2tf(b0.y), f2tf(b1.y));
        *(uint4*)&QP[row][blk * 8 + 4] = make_uint4(f2tf(b0.z), f2tf(b1.z), f2tf(b0.w), f2tf(b1.w));
    }
    __syncthreads();

    // K prefetch registers (4 blocks of 8 floats per thread)
    float4 kp0[4], kp1[4];

    #define LOAD_K(KT) do {                                                     \
        _Pragma("unroll")                                                       \
        for (int u = 0; u < 4; u++) {                                           \
            int bi = tid + u * 256;                                             \
            int row = bi >> 3, blk = bi & 7;                                    \
            const float* p = &kh[(long)((KT) * 128 + row) * D_MOD + blk * 8];   \
            kp0[u] = *(const float4*)p;                                         \
            kp1[u] = *(const float4*)(p + 4);                                   \
        }                                                                       \
    } while (0)

    #define STORE_K() do {                                                      \
        _Pragma("unroll")                                                       \
        for (int u = 0; u < 4; u++) {                                           \
            int bi = tid + u * 256;                                             \
            int row = bi >> 3, blk = bi & 7;                                    \
            *(uint4*)&KP[row][blk * 8]     = make_uint4(f2tf(kp0[u].x), f2tf(kp1[u].x), f2tf(kp0[u].y), f2tf(kp1[u].y)); \
            *(uint4*)&KP[row][blk * 8 + 4] = make_uint4(f2tf(kp0[u].z), f2tf(kp1[u].z), f2tf(kp0[u].w), f2tf(kp1[u].w)); \
        }                                                                       \
    } while (0)

    // S-MMA: acc[16][4] over 128 cols, packed LDS.64 fragments
    #define S_MMA(ACC) do {                                                     \
        _Pragma("unroll")                                                       \
        for (int ks = 0; ks < 8; ks++) {                                        \
            int kc = ks * 8 + 2 * c;                                            \
            uint2 a01 = *(const uint2*)&QP[r][kc];                              \
            uint2 a23 = *(const uint2*)&QP[r + 8][kc];                          \
            unsigned af[4] = {a01.x, a23.x, a01.y, a23.y};                      \
            _Pragma("unroll")                                                   \
            for (int nt = 0; nt < 16; nt++) {                                   \
                uint2 bf = *(const uint2*)&KP[nt * 8 + g][kc];                  \
                mma8(ACC[nt], af, bf.x, bf.y);                                  \
            }                                                                   \
        }                                                                       \
    } while (0)

    float m_0 = -60000.f, m_1 = -60000.f, l_0 = 0.f, l_1 = 0.f;

    // ---------------- pass 1: stats ----------------
    LOAD_K(0);
    for (int kt = 0; kt < 16; kt++) {
        __syncthreads();
        STORE_K();
        __syncthreads();
        if (kt < 15) LOAD_K(kt + 1);

        float acc[16][4] = {};
        S_MMA(acc);

        float t0 = -60000.f, t1 = -60000.f;
        #pragma unroll
        for (int nt = 0; nt < 16; nt++) {
            int col = kt * 128 + nt * 8 + 2 * c;
            bool z0 = (Msk[col] == 0), z1 = (Msk[col + 1] == 0);
            acc[nt][0] = z0 ? -1e9f : acc[nt][0] * 0.125f;
            acc[nt][1] = z1 ? -1e9f : acc[nt][1] * 0.125f;
            acc[nt][2] = z0 ? -1e9f : acc[nt][2] * 0.125f;
            acc[nt][3] = z1 ? -1e9f : acc[nt][3] * 0.125f;
            t0 = fmaxf(t0, fmaxf(acc[nt][0], acc[nt][1]));
            t1 = fmaxf(t1, fmaxf(acc[nt][2], acc[nt][3]));
        }
        t0 = fmaxf(t0, __shfl_xor_sync(0xffffffffu, t0, 1));
        t0 = fmaxf(t0, __shfl_xor_sync(0xffffffffu, t0, 2));
        t1 = fmaxf(t1, __shfl_xor_sync(0xffffffffu, t1, 1));
        t1 = fmaxf(t1, __shfl_xor_sync(0xffffffffu, t1, 2));

        float m0n = fmaxf(m_0, t0), m1n = fmaxf(m_1, t1);
        float s0 = 0.f, s1 = 0.f;
        #pragma unroll
        for (int nt = 0; nt < 16; nt++) {
            s0 += __expf(acc[nt][0] - m0n) + __expf(acc[nt][1] - m0n);
            s1 += __expf(acc[nt][2] - m1n) + __expf(acc[nt][3] - m1n);
        }
        s0 += __shfl_xor_sync(0xffffffffu, s0, 1);
        s0 += __shfl_xor_sync(0xffffffffu, s0, 2);
        s1 += __shfl_xor_sync(0xffffffffu, s1, 1);
        s1 += __shfl_xor_sync(0xffffffffu, s1, 2);

        l_0 = l_0 * __expf(m_0 - m0n) + s0;  m_0 = m0n;
        l_1 = l_1 * __expf(m_1 - m1n) + s1;  m_1 = m1n;
    }

    const float inv0 = 1.f / l_0, inv1 = 1.f / l_1;

    // ---------------- pass 2: P write + PV ----------------
    float accO[8][4] = {};
    float4 vp0[4], vp1[4];

    #define LOAD_V(KT) do {                                                     \
        _Pragma("unroll")                                                       \
        for (int u = 0; u < 4; u++) {                                           \
            int ui = tid + u * 256;                                             \
            int cv = ui & 3, n4 = ((ui >> 2) & 15) * 4, kb = ui >> 6;           \
            const float* p = &vh[(long)((KT) * 128 + kb * 8 + cv) * D_MOD + n4];\
            vp0[u] = *(const float4*)p;                                         \
            vp1[u] = *(const float4*)(p + 4L * D_MOD);                          \
        }                                                                       \
    } while (0)

    #define STORE_V() do {                                                      \
        _Pragma("unroll")                                                       \
        for (int u = 0; u < 4; u++) {                                           \
            int ui = tid + u * 256;                                             \
            int cv = ui & 3, n4 = ((ui >> 2) & 15) * 4, kb = ui >> 6;           \
            int col = kb * 8 + 2 * cv;                                          \
            *(uint2*)&VP[n4][col]     = make_uint2(f2tf(vp0[u].x), f2tf(vp1[u].x)); \
            *(uint2*)&VP[n4 + 1][col] = make_uint2(f2tf(vp0[u].y), f2tf(vp1[u].y)); \
            *(uint2*)&VP[n4 + 2][col] = make_uint2(f2tf(vp0[u].z), f2tf(vp1[u].z)); \
            *(uint2*)&VP[n4 + 3][col] = make_uint2(f2tf(vp0[u].w), f2tf(vp1[u].w)); \
        }                                                                       \
    } while (0)

    LOAD_K(0);
    for (int kt = 0; kt < 16; kt++) {
        __syncthreads();
        STORE_K();
        LOAD_V(kt);                       // LDG in flight across next sync + S-MMA
        __syncthreads();

        float acc[16][4] = {};
        S_MMA(acc);

        STORE_V();
        if (kt < 15) LOAD_K(kt + 1);
        __syncthreads();                  // VP visible to all warps

        // 4 sub-chunks of 32 columns: P -> gmem + warp-private smem, then PV
        #pragma unroll
        for (int sc = 0; sc < 4; sc++) {
            #pragma unroll
            for (int t = 0; t < 4; t++) {
                int nt = sc * 4 + t;
                int col = kt * 128 + nt * 8 + 2 * c;
                bool z0 = (Msk[col] == 0), z1 = (Msk[col + 1] == 0);
                float s0 = z0 ? -1e9f : acc[nt][0] * 0.125f;
                float s1 = z1 ? -1e9f : acc[nt][1] * 0.125f;
                float s2 = z0 ? -1e9f : acc[nt][2] * 0.125f;
                float s3 = z1 ? -1e9f : acc[nt][3] * 0.125f;
                float p0 = __expf(s0 - m_0) * inv0;
                float p1 = __expf(s1 - m_0) * inv0;
                float p2 = __expf(s2 - m_1) * inv1;
                float p3 = __expf(s3 - m_1) * inv1;
                long row0 = (long)(m0 + r) * S_LEN + col;
                *(float2*)&attn_bh[row0]              = make_float2(p0, p1);
                *(float2*)&attn_bh[row0 + 8L * S_LEN] = make_float2(p2, p3);
                int lc = t * 8 + 2 * c;
                Ps[r][lc]         = f2tf(p0);
                Ps[r][lc + 1]     = f2tf(p1);
                Ps[r + 8][lc]     = f2tf(p2);
                Ps[r + 8][lc + 1] = f2tf(p3);
            }
            __syncwarp();
            #pragma unroll
            for (int ks = 0; ks < 4; ks++) {
                int kk = ks * 8;
                unsigned af[4];
                af[0] = Ps[r][kk + c];     af[1] = Ps[r + 8][kk + c];
                af[2] = Ps[r][kk + c + 4]; af[3] = Ps[r + 8][kk + c + 4];
                int kc = (sc * 4 + ks) * 8 + 2 * c;
                #pragma unroll
                for (int on = 0; on < 8; on++) {
                    uint2 bv = *(const uint2*)&VP[on * 8 + g][kc];
                    mma8(accO[on], af, bv.x, bv.y);
                }
            }
            __syncwarp();
        }
    }

    // epilogue: ctx in merged (row, h*64+col) layout
    float* op = ctx + ((long)b * S_LEN + m0 + r) * D_MOD + h * DHEAD;
    #pragma unroll
    for (int on = 0; on < 8; on++) {
        int col = on * 8 + 2 * c;
        *(float2*)&op[col]              = make_float2(accO[on][0], accO[on][1]);
        *(float2*)&op[8L * D_MOD + col] = make_float2(accO[on][2], accO[on][3]);
    }

    #undef LOAD_K
    #undef STORE_K
    #undef S_MMA
    #undef LOAD_V
    #undef STORE_V
}

// ---------------------------------------------------------------------------
extern "C" void kernel_launch(void* const* d_in, const int* in_sizes, int n_in,
                              void* d_out, int out_size)
{
    const float* Q    = (const float*)d_in[0];
    const float* K    = (const float*)d_in[1];
    const float* V    = (const float*)d_in[2];
    const int*   mask = (const int*)  d_in[3];
    const float* Wq   = (const float*)d_in[4];
    const float* bq   = (const float*)d_in[5];
    const float* Wk   = (const float*)d_in[6];
    const float* bk   = (const float*)d_in[7];
    const float* Wv   = (const float*)d_in[8];
    const float* bv   = (const float*)d_in[9];
    const float* Wo   = (const float*)d_in[10];
    const float* bo   = (const float*)d_in[11];

    float* out = (float*)d_out;

    float *q_p, *k_p, *v_p, *ctx_p, *attn_scr;
    cudaGetSymbolAddress((void**)&q_p,      g_q);
    cudaGetSymbolAddress((void**)&k_p,      g_k);
    cudaGetSymbolAddress((void**)&v_p,      g_v);
    cudaGetSymbolAddress((void**)&ctx_p,    g_ctx);
    cudaGetSymbolAddress((void**)&attn_scr, g_attn_scratch);

    float* attn = ((long)out_size >= OUT_ELEMS + ATTN_ELEMS)
                      ? (out + OUT_ELEMS) : attn_scr;

    cudaFuncSetAttribute(fused_attn,
                         cudaFuncAttributeMaxDynamicSharedMemorySize, SMEM_BYTES);

    dim3 projGrid(D_MOD / 128, MROWS / 128);          // (8, 32)
    proj_mma<<<projGrid, 256>>>(Q, Wq, bq, q_p);
    proj_mma<<<projGrid, 256>>>(K, Wk, bk, k_p);
    proj_mma<<<projGrid, 256>>>(V, Wv, bv, v_p);

    dim3 attnGrid(S_LEN / 128, B_SZ * HEADS);         // (16, 32)
    fused_attn<<<attnGrid, 256, SMEM_BYTES>>>(q_p, k_p, v_p, mask, attn, ctx_p);

    proj_mma<<<projGrid, 256>>>(ctx_p, Wo, bo, out);
}

// round 17
// speedup vs baseline: 1.6229x; 1.6229x over previous
#include <cuda_runtime.h>
#include <cuda_fp16.h>

// Problem constants
#define B_SZ   2
#define S_LEN  2048
#define D_MOD  1024
#define HEADS  16
#define DHEAD  64
#define MROWS  (B_SZ * S_LEN)                                 // 4096
#define OUT_ELEMS  ((long)MROWS * D_MOD)                      // 4194304
#define ATTN_ELEMS ((long)B_SZ * HEADS * S_LEN * S_LEN)       // 134217728

// Scratch (static __device__ arrays: allocation-free per harness rules)
__device__ float g_q[MROWS * D_MOD];
__device__ float g_k[MROWS * D_MOD];
__device__ float g_v[MROWS * D_MOD];
__device__ float g_ctx[MROWS * D_MOD];
__device__ float g_attn_scratch[ATTN_ELEMS];

// ---------------------------------------------------------------------------
// helpers
// ---------------------------------------------------------------------------
__device__ __forceinline__ unsigned f2tf(float f) {
    unsigned u;
    asm("cvt.rna.tf32.f32 %0, %1;" : "=r"(u) : "f"(f));
    return u;
}
__device__ __forceinline__ uint4 cvt4(float4 f) {
    return make_uint4(f2tf(f.x), f2tf(f.y), f2tf(f.z), f2tf(f.w));
}
__device__ __forceinline__ void mma8(float* d, const unsigned* a, unsigned b0, unsigned b1) {
    asm volatile(
        "mma.sync.aligned.m16n8k8.row.col.f32.tf32.tf32.f32 "
        "{%0,%1,%2,%3}, {%4,%5,%6,%7}, {%8,%9}, {%0,%1,%2,%3};\n"
        : "+f"(d[0]), "+f"(d[1]), "+f"(d[2]), "+f"(d[3])
        : "r"(a[0]), "r"(a[1]), "r"(a[2]), "r"(a[3]), "r"(b0), "r"(b1));
}
__device__ __forceinline__ void mma16h(float* d, const unsigned* a, unsigned b0, unsigned b1) {
    asm volatile(
        "mma.sync.aligned.m16n8k16.row.col.f32.f16.f16.f32 "
        "{%0,%1,%2,%3}, {%4,%5,%6,%7}, {%8,%9}, {%0,%1,%2,%3};\n"
        : "+f"(d[0]), "+f"(d[1]), "+f"(d[2]), "+f"(d[3])
        : "r"(a[0]), "r"(a[1]), "r"(a[2]), "r"(a[3]), "r"(b0), "r"(b1));
}
__device__ __forceinline__ unsigned pack_h2(float lo, float hi) {
    __half2 h = __floats2half2_rn(lo, hi);
    return *(unsigned*)&h;
}

// ---------------------------------------------------------------------------
// proj_mma: C[m][n] = A[m][k] * W[n][k] + bias[n]   (GEMM-NT)  — proven R1/R2
// ---------------------------------------------------------------------------
__global__ __launch_bounds__(256, 2) void proj_mma(
    const float* __restrict__ A, const float* __restrict__ W,
    const float* __restrict__ bias, float* __restrict__ C)
{
    __shared__ unsigned As[128][36];
    __shared__ unsigned Ws[128][36];

    const int tid = threadIdx.x;
    const int wid = tid >> 5, lane = tid & 31;
    const int g = lane >> 2, c = lane & 3;
    const int wm = wid >> 2;
    const int wn = wid & 3;
    const int m0 = blockIdx.y * 128, n0 = blockIdx.x * 128;

    float acc[4][4][4] = {};

    for (int k0 = 0; k0 < D_MOD; k0 += 32) {
        #pragma unroll
        for (int i = 0; i < 4; i++) {
            int idx = tid + i * 256;
            int row = idx >> 3, c4 = (idx & 7) * 4;
            float4 fa = *(const float4*)&A[(long)(m0 + row) * D_MOD + k0 + c4];
            float4 fw = *(const float4*)&W[(long)(n0 + row) * D_MOD + k0 + c4];
            *(uint4*)&As[row][c4] = cvt4(fa);
            *(uint4*)&Ws[row][c4] = cvt4(fw);
        }
        __syncthreads();

        #pragma unroll
        for (int ks = 0; ks < 4; ks++) {
            int kk = ks * 8;
            unsigned af[4][4], bf[4][2];
            #pragma unroll
            for (int mt = 0; mt < 4; mt++) {
                int r = wm * 64 + mt * 16 + g;
                af[mt][0] = As[r][kk + c];     af[mt][1] = As[r + 8][kk + c];
                af[mt][2] = As[r][kk + c + 4]; af[mt][3] = As[r + 8][kk + c + 4];
            }
            #pragma unroll
            for (int nt = 0; nt < 4; nt++) {
                int n = wn * 32 + nt * 8 + g;
                bf[nt][0] = Ws[n][kk + c];
                bf[nt][1] = Ws[n][kk + c + 4];
            }
            #pragma unroll
            for (int mt = 0; mt < 4; mt++)
                #pragma unroll
                for (int nt = 0; nt < 4; nt++)
                    mma8(acc[mt][nt], af[mt], bf[nt][0], bf[nt][1]);
        }
        __syncthreads();
    }

    #pragma unroll
    for (int nt = 0; nt < 4; nt++) {
        int col = n0 + wn * 32 + nt * 8 + 2 * c;
        float b0 = bias[col], b1 = bias[col + 1];
        #pragma unroll
        for (int mt = 0; mt < 4; mt++) {
            int r0 = m0 + wm * 64 + mt * 16 + g;
            float2 v0 = {acc[mt][nt][0] + b0, acc[mt][nt][1] + b1};
            float2 v1 = {acc[mt][nt][2] + b0, acc[mt][nt][3] + b1};
            *(float2*)&C[(long)r0 * D_MOD + col]       = v0;
            *(float2*)&C[(long)(r0 + 8) * D_MOD + col] = v1;
        }
    }
}

// ---------------------------------------------------------------------------
// Fused attention v5 (fp16 fragments, fp32 softmax/accum):
// R6 structure (128-wide tiles, 2-pass flash, warp = 16 rows x 128 cols),
// m16n8k16.f16 MMAs. smem words = half2 (k-pair), word indices identical to
// the proven tf32 pattern. S processed in two 64-col halves (register cap).
// 80KB smem + launch_bounds(256,2) -> 2 CTAs/SM.
// ---------------------------------------------------------------------------
#define QS_OFF   0                        // 128*36*4 = 18432
#define KS_OFF   18432                    // 18432
#define VS_OFF   36864                    // 64*72*4  = 18432
#define PS_OFF   55296                    // 128*36*4 = 18432
#define MSK_OFF  73728                    // 8192
#define SMEM_BYTES 81920

__global__ __launch_bounds__(256, 2) void fused_attn(
    const float* __restrict__ q, const float* __restrict__ k,
    const float* __restrict__ v, const int* __restrict__ mask,
    float* __restrict__ attn, float* __restrict__ ctx)
{
    extern __shared__ char sm[];
    unsigned (*QH)[36] = (unsigned(*)[36])(sm + QS_OFF);   // [128 m][32 kw] h2
    unsigned (*KH)[36] = (unsigned(*)[36])(sm + KS_OFF);   // [128 n][32 kw] h2
    unsigned (*VF)[72] = (unsigned(*)[72])(sm + VS_OFF);   // [64 kp][64 n] h2 (k-pair major)
    unsigned (*PH)[36] = (unsigned(*)[36])(sm + PS_OFF);   // [128 m][32 kw] h2
    int* Msk = (int*)(sm + MSK_OFF);

    const int bh = blockIdx.y;
    const int b = bh >> 4, h = bh & 15;
    const float* qh = q + (long)b * S_LEN * D_MOD + h * DHEAD;
    const float* kh = k + (long)b * S_LEN * D_MOD + h * DHEAD;
    const float* vh = v + (long)b * S_LEN * D_MOD + h * DHEAD;
    float* attn_bh = attn + (long)bh * S_LEN * S_LEN;

    const int tid = threadIdx.x;
    const int wid = tid >> 5, lane = tid & 31;
    const int g = lane >> 2, c = lane & 3;
    const int m0 = blockIdx.x * 128;
    const int r = wid * 16 + g;        // warp-local rows r and r+8

    for (int j = tid; j < S_LEN; j += 256)
        Msk[j] = mask[b * S_LEN + j];

    // ---- Q tile: load + fp16 pack (one-time). word j = halves(k=2j, 2j+1) ----
    #pragma unroll
    for (int u = 0; u < 4; u++) {
        int bi = tid + u * 256;
        int row = bi >> 3, blk = bi & 7;
        const float* p = &qh[(long)(m0 + row) * D_MOD + blk * 8];
        float4 b0 = *(const float4*)p;
        float4 b1 = *(const float4*)(p + 4);
        *(uint4*)&QH[row][blk * 4] = make_uint4(pack_h2(b0.x, b0.y), pack_h2(b0.z, b0.w),
                                                pack_h2(b1.x, b1.y), pack_h2(b1.z, b1.w));
    }
    __syncthreads();

    // K tile loader (LDG + cvt + STS, between barriers — no prefetch regs)
    #define LOADSTORE_K(KT) do {                                                \
        _Pragma("unroll")                                                       \
        for (int u = 0; u < 4; u++) {                                           \
            int bi = tid + u * 256;                                             \
            int row = bi >> 3, blk = bi & 7;                                    \
            const float* p = &kh[(long)((KT) * 128 + row) * D_MOD + blk * 8];   \
            float4 b0 = *(const float4*)p;                                      \
            float4 b1 = *(const float4*)(p + 4);                                \
            *(uint4*)&KH[row][blk * 4] = make_uint4(pack_h2(b0.x, b0.y), pack_h2(b0.z, b0.w), \
                                                    pack_h2(b1.x, b1.y), pack_h2(b1.z, b1.w)); \
        }                                                                       \
    } while (0)

    // V tile loader: VF[kp][n] = halves(v[2kp][n], v[2kp+1][n])
    #define LOADSTORE_V(KT) do {                                                \
        _Pragma("unroll")                                                       \
        for (int u = 0; u < 4; u++) {                                           \
            int ui = tid + u * 256;                                             \
            int kp = ui >> 4, n4 = (ui & 15) * 4;                               \
            const float* p0 = &vh[(long)((KT) * 128 + 2 * kp) * D_MOD + n4];    \
            float4 v0 = *(const float4*)p0;                                     \
            float4 v1 = *(const float4*)(p0 + D_MOD);                           \
            VF[kp][n4 + 0] = pack_h2(v0.x, v1.x);                               \
            VF[kp][n4 + 1] = pack_h2(v0.y, v1.y);                               \
            VF[kp][n4 + 2] = pack_h2(v0.z, v1.z);                               \
            VF[kp][n4 + 3] = pack_h2(v0.w, v1.w);                               \
        }                                                                       \
    } while (0)

    // S half-tile: 64 cols (nt local 0..7 at NT0 offset), k=64 via 4 m16n8k16
    #define S_MMA_HALF(ACC, NT0) do {                                           \
        _Pragma("unroll")                                                       \
        for (int kb = 0; kb < 4; kb++) {                                        \
            int kc = kb * 8;                                                    \
            unsigned af[4];                                                     \
            af[0] = QH[r][kc + c];     af[1] = QH[r + 8][kc + c];               \
            af[2] = QH[r][kc + c + 4]; af[3] = QH[r + 8][kc + c + 4];           \
            _Pragma("unroll")                                                   \
            for (int nt = 0; nt < 8; nt++) {                                    \
                int n = ((NT0) + nt) * 8 + g;                                   \
                mma16h(ACC[nt], af, KH[n][kc + c], KH[n][kc + c + 4]);          \
            }                                                                   \
        }                                                                       \
    } while (0)

    float m_0 = -60000.f, m_1 = -60000.f, l_0 = 0.f, l_1 = 0.f;

    // ---------------- pass 1: stats ----------------
    for (int kt = 0; kt < 16; kt++) {
        __syncthreads();
        LOADSTORE_K(kt);
        __syncthreads();

        #pragma unroll
        for (int hf = 0; hf < 2; hf++) {
            float acc[8][4] = {};
            S_MMA_HALF(acc, hf * 8);

            float t0 = -60000.f, t1 = -60000.f;
            #pragma unroll
            for (int nt = 0; nt < 8; nt++) {
                int col = kt * 128 + (hf * 8 + nt) * 8 + 2 * c;
                bool z0 = (Msk[col] == 0), z1 = (Msk[col + 1] == 0);
                acc[nt][0] = z0 ? -1e9f : acc[nt][0] * 0.125f;
                acc[nt][1] = z1 ? -1e9f : acc[nt][1] * 0.125f;
                acc[nt][2] = z0 ? -1e9f : acc[nt][2] * 0.125f;
                acc[nt][3] = z1 ? -1e9f : acc[nt][3] * 0.125f;
                t0 = fmaxf(t0, fmaxf(acc[nt][0], acc[nt][1]));
                t1 = fmaxf(t1, fmaxf(acc[nt][2], acc[nt][3]));
            }
            t0 = fmaxf(t0, __shfl_xor_sync(0xffffffffu, t0, 1));
            t0 = fmaxf(t0, __shfl_xor_sync(0xffffffffu, t0, 2));
            t1 = fmaxf(t1, __shfl_xor_sync(0xffffffffu, t1, 1));
            t1 = fmaxf(t1, __shfl_xor_sync(0xffffffffu, t1, 2));

            float m0n = fmaxf(m_0, t0), m1n = fmaxf(m_1, t1);
            float s0 = 0.f, s1 = 0.f;
            #pragma unroll
            for (int nt = 0; nt < 8; nt++) {
                s0 += __expf(acc[nt][0] - m0n) + __expf(acc[nt][1] - m0n);
                s1 += __expf(acc[nt][2] - m1n) + __expf(acc[nt][3] - m1n);
            }
            s0 += __shfl_xor_sync(0xffffffffu, s0, 1);
            s0 += __shfl_xor_sync(0xffffffffu, s0, 2);
            s1 += __shfl_xor_sync(0xffffffffu, s1, 1);
            s1 += __shfl_xor_sync(0xffffffffu, s1, 2);

            l_0 = l_0 * __expf(m_0 - m0n) + s0;  m_0 = m0n;
            l_1 = l_1 * __expf(m_1 - m1n) + s1;  m_1 = m1n;
        }
    }

    const float inv0 = 1.f / l_0, inv1 = 1.f / l_1;

    // ---------------- pass 2: P write + PV ----------------
    float accO[8][4] = {};

    for (int kt = 0; kt < 16; kt++) {
        __syncthreads();
        LOADSTORE_K(kt);
        LOADSTORE_V(kt);
        __syncthreads();

        #pragma unroll
        for (int hf = 0; hf < 2; hf++) {
            float acc[8][4] = {};
            S_MMA_HALF(acc, hf * 8);

            // P: normalize, write attn (gmem) + PH (warp-private smem, fp16)
            #pragma unroll
            for (int nt = 0; nt < 8; nt++) {
                int col = kt * 128 + (hf * 8 + nt) * 8 + 2 * c;
                bool z0 = (Msk[col] == 0), z1 = (Msk[col + 1] == 0);
                float s0 = z0 ? -1e9f : acc[nt][0] * 0.125f;
                float s1 = z1 ? -1e9f : acc[nt][1] * 0.125f;
                float s2 = z0 ? -1e9f : acc[nt][2] * 0.125f;
                float s3 = z1 ? -1e9f : acc[nt][3] * 0.125f;
                float p0 = __expf(s0 - m_0) * inv0;
                float p1 = __expf(s1 - m_0) * inv0;
                float p2 = __expf(s2 - m_1) * inv1;
                float p3 = __expf(s3 - m_1) * inv1;
                long row0 = (long)(m0 + r) * S_LEN + col;
                *(float2*)&attn_bh[row0]              = make_float2(p0, p1);
                *(float2*)&attn_bh[row0 + 8L * S_LEN] = make_float2(p2, p3);
                PH[r][nt * 4 + c]     = pack_h2(p0, p1);
                PH[r + 8][nt * 4 + c] = pack_h2(p2, p3);
            }
            __syncwarp();

            // PV: O += P_half(128x64k) @ V_half(64k x 64n), fp16 MMA
            #pragma unroll
            for (int kb = 0; kb < 4; kb++) {
                int kc = kb * 8;
                unsigned af[4];
                af[0] = PH[r][kc + c];     af[1] = PH[r + 8][kc + c];
                af[2] = PH[r][kc + c + 4]; af[3] = PH[r + 8][kc + c + 4];
                int kp0 = hf * 32 + kb * 8 + c;
                #pragma unroll
                for (int on = 0; on < 8; on++) {
                    int n = on * 8 + g;
                    mma16h(accO[on], af, VF[kp0][n], VF[kp0 + 4][n]);
                }
            }
            __syncwarp();
        }
    }

    // epilogue: ctx in merged (row, h*64+col) layout
    float* op = ctx + ((long)b * S_LEN + m0 + r) * D_MOD + h * DHEAD;
    #pragma unroll
    for (int on = 0; on < 8; on++) {
        int col = on * 8 + 2 * c;
        *(float2*)&op[col]              = make_float2(accO[on][0], accO[on][1]);
        *(float2*)&op[8L * D_MOD + col] = make_float2(accO[on][2], accO[on][3]);
    }

    #undef LOADSTORE_K
    #undef LOADSTORE_V
    #undef S_MMA_HALF
}

// ---------------------------------------------------------------------------
extern "C" void kernel_launch(void* const* d_in, const int* in_sizes, int n_in,
                              void* d_out, int out_size)
{
    const float* Q    = (const float*)d_in[0];
    const float* K    = (const float*)d_in[1];
    const float* V    = (const float*)d_in[2];
    const int*   mask = (const int*)  d_in[3];
    const float* Wq   = (const float*)d_in[4];
    const float* bq   = (const float*)d_in[5];
    const float* Wk   = (const float*)d_in[6];
    const float* bk   = (const float*)d_in[7];
    const float* Wv   = (const float*)d_in[8];
    const float* bv   = (const float*)d_in[9];
    const float* Wo   = (const float*)d_in[10];
    const float* bo   = (const float*)d_in[11];

    float* out = (float*)d_out;

    float *q_p, *k_p, *v_p, *ctx_p, *attn_scr;
    cudaGetSymbolAddress((void**)&q_p,      g_q);
    cudaGetSymbolAddress((void**)&k_p,      g_k);
    cudaGetSymbolAddress((void**)&v_p,      g_v);
    cudaGetSymbolAddress((void**)&ctx_p,    g_ctx);
    cudaGetSymbolAddress((void**)&attn_scr, g_attn_scratch);

    float* attn = ((long)out_size >= OUT_ELEMS + ATTN_ELEMS)
                      ? (out + OUT_ELEMS) : attn_scr;

    cudaFuncSetAttribute(fused_attn,
                         cudaFuncAttributeMaxDynamicSharedMemorySize, SMEM_BYTES);

    dim3 projGrid(D_MOD / 128, MROWS / 128);          // (8, 32)
    proj_mma<<<projGrid, 256>>>(Q, Wq, bq, q_p);
    proj_mma<<<projGrid, 256>>>(K, Wk, bk, k_p);
    proj_mma<<<projGrid, 256>>>(V, Wv, bv, v_p);

    dim3 attnGrid(S_LEN / 128, B_SZ * HEADS);         // (16, 32)
    fused_attn<<<attnGrid, 256, SMEM_BYTES>>>(q_p, k_p, v_p, mask, attn, ctx_p);

    proj_mma<<<projGrid, 256>>>(ctx_p, Wo, bo, out);
}